// round 15
// baseline (speedup 1.0000x reference)
#include <cuda_runtime.h>
#include <cuda_bf16.h>
#include <cuda_fp16.h>
#include <cstdint>

// Problem constants
#define BB 2
#define NN 2048
#define EE 2048
#define HH 16
#define DD 128
#define MTOT (BB * NN)
#define SCALE 0.08838834764831843f

// ---------------------------------------------------------------------------
// Device scratch (allocation-free rule)
// ---------------------------------------------------------------------------
__device__ __half g_qf[(size_t)BB * HH * NN * DD];   // Q fp16 [B,H,N,D] (pre-scaled)
__device__ __half g_kf[(size_t)BB * HH * NN * DD];   // K fp16 [B,H,N,D]
__device__ __half g_vtf[(size_t)BB * HH * DD * NN];  // V fp16 [B,H,D,N]

__device__ __half s_xf[8388608];    // x    fp16 [M,K]
__device__ __half s_wqf[4194304];   // Wq   fp16 [E,K]
__device__ __half s_wkf[8388608];   // Wkv  fp16 [2E,K]
__device__ __half s_wof[4194304];   // Wout fp16 [E,K]
__device__ __half s_af[8388608];    // attn fp16 [B,N,E]

// ---------------------------------------------------------------------------
// Helpers
// ---------------------------------------------------------------------------
__device__ __forceinline__ uint32_t smem_u32(const void* p) {
    uint32_t a;
    asm("{ .reg .u64 t; cvta.to.shared.u64 t, %1; cvt.u32.u64 %0, t; }"
        : "=r"(a) : "l"(p));
    return a;
}
__device__ __forceinline__ void cp16(uint32_t dst, const void* src) {
    asm volatile("cp.async.cg.shared.global [%0], [%1], 16;"
                 :: "r"(dst), "l"(src));
}
__device__ __forceinline__ void cp_commit() {
    asm volatile("cp.async.commit_group;");
}
__device__ __forceinline__ uint32_t sw128(uint32_t off) {  // SW128 for 128B rows
    return off ^ ((off >> 3) & 0x70);
}
__device__ __forceinline__ void ldmx4(uint32_t* f, uint32_t addr) {
    asm volatile("ldmatrix.sync.aligned.m8n8.x4.shared.b16 {%0,%1,%2,%3}, [%4];"
                 : "=r"(f[0]), "=r"(f[1]), "=r"(f[2]), "=r"(f[3]) : "r"(addr));
}
// fp16 MMA
__device__ __forceinline__ void mma16816h(float* c, const uint32_t* a,
                                          uint32_t b0, uint32_t b1) {
    asm volatile(
        "mma.sync.aligned.m16n8k16.row.col.f32.f16.f16.f32 "
        "{%0,%1,%2,%3}, {%4,%5,%6,%7}, {%8,%9}, {%0,%1,%2,%3};"
        : "+f"(c[0]), "+f"(c[1]), "+f"(c[2]), "+f"(c[3])
        : "r"(a[0]), "r"(a[1]), "r"(a[2]), "r"(a[3]), "r"(b0), "r"(b1));
}
__device__ __forceinline__ uint32_t packhf(float a, float b) {
    __half2 t = __floats2half2_rn(a, b);
    return *(uint32_t*)&t;
}

// ---------------------------------------------------------------------------
// Merged convert kernel: all four fp32 inputs -> fp16 in one launch
// ---------------------------------------------------------------------------
#define N4_X  2097152
#define N4_WQ 1048576
#define N4_WK 2097152
#define N4_WO 1048576
#define N4_TOT (N4_X + N4_WQ + N4_WK + N4_WO)   // 6291456

__global__ __launch_bounds__(256) void split_all_kernel(
    const float* __restrict__ x, const float* __restrict__ wq,
    const float* __restrict__ wk, const float* __restrict__ wo)
{
    int i = blockIdx.x * blockDim.x + threadIdx.x;
    if (i >= N4_TOT) return;
    const float* src;
    __half* dst;
    int off;
    if (i < N4_X) {
        src = x; dst = s_xf; off = i;
    } else if (i < N4_X + N4_WQ) {
        src = wq; dst = s_wqf; off = i - N4_X;
    } else if (i < N4_X + N4_WQ + N4_WK) {
        src = wk; dst = s_wkf; off = i - N4_X - N4_WQ;
    } else {
        src = wo; dst = s_wof; off = i - N4_X - N4_WQ - N4_WK;
    }
    float4 v = ((const float4*)src)[off];
    __half h[4];
    h[0] = __float2half(v.x); h[1] = __float2half(v.y);
    h[2] = __float2half(v.z); h[3] = __float2half(v.w);
    ((uint2*)dst)[off] = *(const uint2*)h;
}

// ---------------------------------------------------------------------------
// fp16 single-pass GEMM via mma.sync.
// K-chunk 64 (128B rows, SW128), 3-stage cp.async ring, ONE barrier/iter.
// MODE 0: Cout fp32 [M,E]  (Wout projection: A=s_af, W=s_wof)
// MODE 3: merged QKV: blockIdx.x selects Q / K / V target + weight matrix
// ---------------------------------------------------------------------------
#define GTILE 16384                // 128 rows x 128B (64 fp16)
#define GSTAGE (2 * GTILE)         // 32768
#define GEMM_SMEM 98304            // 3 stages; epilogue (67584) reuses

__device__ __forceinline__ void load_chunk(
    uint32_t stage, const __half* Af, const __half* Wf,
    int m0, int wrow0, int k0, int tid)
{
#pragma unroll
    for (int t = 0; t < 4; ++t) {
        const int c = tid + t * 256;           // 0..1023 : 16B chunks per tile
        const int row = c >> 3;
        const int ch = c & 7;
        const uint32_t so = sw128((uint32_t)(row * 128 + ch * 16));
        cp16(stage + so, Af + (size_t)(m0 + row) * EE + k0 + ch * 8);
        cp16(stage + GTILE + so, Wf + (size_t)(wrow0 + row) * EE + k0 + ch * 8);
    }
}

template <int MODE>
__global__ void __launch_bounds__(256) gemm_mma(
    const __half* __restrict__ Af,
    const __half* __restrict__ Wqf, const __half* __restrict__ Wkf,
    float* __restrict__ Cout)
{
    extern __shared__ char smem[];
    const uint32_t sb = smem_u32(smem);
    const int tid = threadIdx.x;
    const int lane = tid & 31;
    const int w = tid >> 5;
    const int wm = w >> 2;
    const int wn = w & 3;
    const int m0 = blockIdx.y * 128;
    const int n0 = blockIdx.x * 128;

    const __half* Wf;
    int wrow0, ek;
    if (MODE == 0) {
        Wf = Wqf; wrow0 = n0; ek = 3;
    } else {
        if (n0 < EE) { Wf = Wqf; wrow0 = n0; ek = 0; }
        else {
            Wf = Wkf; wrow0 = n0 - EE;
            ek = (wrow0 < EE) ? 1 : 2;
        }
    }

    float acc[4][4][4];
#pragma unroll
    for (int i = 0; i < 4; ++i)
#pragma unroll
        for (int j = 0; j < 4; ++j)
#pragma unroll
            for (int r = 0; r < 4; ++r) acc[i][j][r] = 0.0f;

    const int sel = lane >> 3;
    const int lrow8 = ((sel & 1) << 3) + (lane & 7);
    const int lkc = sel >> 1;

    const int nk = EE >> 6;     // 32 iterations of K=64
    load_chunk(sb + 0 * GSTAGE, Af, Wf, m0, wrow0, 0, tid);
    cp_commit();
    load_chunk(sb + 1 * GSTAGE, Af, Wf, m0, wrow0, 64, tid);
    cp_commit();

    int stg_idx = 0;
    for (int kt = 0; kt < nk; ++kt) {
        const uint32_t stage = sb + stg_idx * GSTAGE;

        // stage kt is complete when at most 1 newer group is outstanding
        asm volatile("cp.async.wait_group 1;");
        __syncthreads();

        // Prefetch kt+2 into the stage read at kt-1 (all reads done pre-barrier)
        if (kt + 2 < nk) {
            int nidx = stg_idx + 2; if (nidx >= 3) nidx -= 3;
            load_chunk(sb + nidx * GSTAGE, Af, Wf, m0, wrow0, (kt + 2) << 6, tid);
            cp_commit();
        }

#pragma unroll
        for (int ks = 0; ks < 4; ++ks) {
            const int kchunk = ks * 2 + lkc;
            uint32_t af[4][4];
#pragma unroll
            for (int i = 0; i < 4; ++i) {
                const int r = wm * 64 + i * 16 + lrow8;
                const uint32_t off = sw128((uint32_t)(r * 128 + kchunk * 16));
                ldmx4(af[i], stage + off);
            }
            uint32_t bf[2][4];
#pragma unroll
            for (int j2 = 0; j2 < 2; ++j2) {
                const int r = wn * 32 + j2 * 16 + lrow8;
                const uint32_t off = sw128((uint32_t)(r * 128 + kchunk * 16));
                ldmx4(bf[j2], stage + GTILE + off);
            }
#pragma unroll
            for (int i = 0; i < 4; ++i) {
#pragma unroll
                for (int j = 0; j < 4; ++j) {
                    const int j2 = j >> 1, jo = j & 1;
                    mma16816h(acc[i][j], af[i], bf[j2][jo], bf[j2][2 + jo]);
                }
            }
        }
        ++stg_idx; if (stg_idx >= 3) stg_idx = 0;
    }
    __syncthreads();   // protect epilogue smem reuse vs last stage reads

    // ---- Epilogue ----
    float* Ss = (float*)smem;   // [128][132]
#pragma unroll
    for (int i = 0; i < 4; ++i) {
        const int r = wm * 64 + i * 16 + (lane >> 2);
#pragma unroll
        for (int j = 0; j < 4; ++j) {
            const int cc = wn * 32 + j * 8 + 2 * (lane & 3);
            Ss[r * 132 + cc]           = acc[i][j][0];
            Ss[r * 132 + cc + 1]       = acc[i][j][1];
            Ss[(r + 8) * 132 + cc]     = acc[i][j][2];
            Ss[(r + 8) * 132 + cc + 1] = acc[i][j][3];
        }
    }
    __syncthreads();

    const int b = m0 >> 11;
    const int nbase = m0 & (NN - 1);

    if (ek == 3) {
#pragma unroll
        for (int it = 0; it < 16; ++it) {
            const int f = it * 256 + tid;
            const int r = f >> 5;
            const int c4 = (f & 31) << 2;
            float4 v = *(const float4*)(Ss + r * 132 + c4);
            *(float4*)(Cout + (size_t)(m0 + r) * EE + n0 + c4) = v;
        }
    } else if (ek == 0 || ek == 1) {
        const int h = wrow0 >> 7;
        __half* dq = (ek == 0 ? g_qf : g_kf) +
            ((size_t)(b * HH + h) * NN + nbase) * DD;
        const float sc = (ek == 0) ? SCALE : 1.0f;   // pre-scale Q by D^-0.5
#pragma unroll
        for (int it = 0; it < 16; ++it) {
            const int f = it * 256 + tid;
            const int r = f >> 5;
            const int c4 = (f & 31) << 2;
            float4 v = *(const float4*)(Ss + r * 132 + c4);
            __half hq[4];
            hq[0] = __float2half(v.x * sc); hq[1] = __float2half(v.y * sc);
            hq[2] = __float2half(v.z * sc); hq[3] = __float2half(v.w * sc);
            *(uint2*)(dq + (size_t)r * DD + c4) = *(const uint2*)hq;
        }
    } else {
        // V -> g_vtf fp16, transposed [B,H,D,N]
        const int h2 = (wrow0 - EE) >> 7;
        const int col = tid >> 1;
        const int rh2 = tid & 1;
        __half* dst = g_vtf + ((size_t)(b * HH + h2) * DD + col) * NN +
                      nbase + (rh2 << 6);
#pragma unroll
        for (int i = 0; i < 16; ++i) {
            const int r = (rh2 << 6) + (i << 2);
            __half v4[4];
            v4[0] = __float2half(Ss[(r + 0) * 132 + col]);
            v4[1] = __float2half(Ss[(r + 1) * 132 + col]);
            v4[2] = __float2half(Ss[(r + 2) * 132 + col]);
            v4[3] = __float2half(Ss[(r + 3) * 132 + col]);
            *(uint2*)(dst + (i << 2)) = *(const uint2*)v4;
        }
    }
}

// ---------------------------------------------------------------------------
// Flash attention v3: single-pass fp16 mma.sync for QK^T and PV.
// Br=128 (8 warps x 16 rows), Bc=64, D=128. 2 CTAs/SM.
// ONE barrier per KV tile (prefetch issued after barrier).
// Q pre-scaled by D^-0.5 at projection — no scale loop here.
// Smem: Q [128x272B] | 2 stages of {K 64x272B; Vt 128x144B}
// ---------------------------------------------------------------------------
#define FQ_BYTES 34816              // 128*272
#define FK_BYTES 17408              // 64*272
#define FV_BYTES 18432              // 128*144
#define FSTAGE (FK_BYTES + FV_BYTES)                // 35840
#define FLASH2_SMEM (FQ_BYTES + 2 * FSTAGE)         // 106496

__device__ __forceinline__ void load_kv(
    uint32_t stg, const __half* Kf, const __half* Vf, int j0, int tid)
{
#pragma unroll
    for (int t = 0; t < 4; ++t) {
        const int c = t * 256 + tid;        // 0..1023
        const int row = c >> 4, ch = c & 15;
        cp16(stg + row * 272 + ch * 16,
             Kf + (size_t)(j0 + row) * DD + ch * 8);
    }
#pragma unroll
    for (int t = 0; t < 4; ++t) {
        const int c = t * 256 + tid;        // 0..1023
        const int drow = c >> 3, ch = c & 7;
        cp16(stg + FK_BYTES + drow * 144 + ch * 16,
             Vf + (size_t)drow * NN + j0 + ch * 8);
    }
}

__global__ void __launch_bounds__(256, 2) flash_mma()
{
    extern __shared__ char smc[];
    const uint32_t sb = smem_u32(smc);
    const int tid = threadIdx.x;
    const int lane = tid & 31;
    const int w = tid >> 5;
    const int bh = blockIdx.y;
    const int b = bh >> 4, h = bh & (HH - 1);
    const int qt = (gridDim.x - 1) - blockIdx.x;   // long tiles first
    const int i0 = qt * 128;

    const __half* Qf = g_qf + (size_t)bh * NN * DD;
    const __half* Kf = g_kf + (size_t)bh * NN * DD;
    const __half* Vf = g_vtf + (size_t)bh * DD * NN;

    // Q tile
#pragma unroll
    for (int t = 0; t < 8; ++t) {
        const int c = t * 256 + tid;        // 0..2047
        const int row = c >> 4, ch = c & 15;
        cp16(sb + row * 272 + ch * 16,
             Qf + (size_t)(i0 + row) * DD + ch * 8);
    }
    load_kv(sb + FQ_BYTES, Kf, Vf, 0, tid);
    cp_commit();

    const int nj = 2 * qt + 2;
    float m_[2] = {-1e30f, -1e30f}, l_[2] = {0.0f, 0.0f};
    float O[16][4];
#pragma unroll
    for (int nt = 0; nt < 16; ++nt)
#pragma unroll
        for (int r = 0; r < 4; ++r) O[nt][r] = 0.0f;

    const int r0 = w * 16 + (lane >> 2);

    for (int jt = 0; jt < nj; ++jt) {
        const uint32_t stg = sb + FQ_BYTES + (jt & 1) * FSTAGE;

        asm volatile("cp.async.wait_group 0;");
        __syncthreads();

        // Prefetch next KV into the stage read at jt-1 (reads done pre-barrier)
        if (jt + 1 < nj) {
            load_kv(sb + FQ_BYTES + ((jt + 1) & 1) * FSTAGE,
                    Kf, Vf, (jt + 1) * 64, tid);
            cp_commit();
        }

        // ---- S = Q K^T (single-pass fp16; Q pre-scaled) ----
        float S[8][4];
#pragma unroll
        for (int nt = 0; nt < 8; ++nt)
#pragma unroll
            for (int r = 0; r < 4; ++r) S[nt][r] = 0.0f;

        const int lrA = w * 16 + ((lane >> 3) & 1) * 8 + (lane & 7);
        const int cA16 = (lane >> 4) & 1;
        const int lrB = ((lane >> 4) & 1) * 8 + (lane & 7);
        const int cB16 = (lane >> 3) & 1;

#pragma unroll
        for (int ks = 0; ks < 8; ++ks) {
            uint32_t aq[4];
            ldmx4(aq, sb + lrA * 272 + ks * 32 + cA16 * 16);
#pragma unroll
            for (int jn2 = 0; jn2 < 4; ++jn2) {
                uint32_t bk[4];
                ldmx4(bk, stg + (jn2 * 16 + lrB) * 272 + ks * 32 + cB16 * 16);
                mma16816h(S[2 * jn2],     aq, bk[0], bk[1]);
                mma16816h(S[2 * jn2 + 1], aq, bk[2], bk[3]);
            }
        }

        // ---- causal mask (last two KV tiles only) ----
        const int j0 = jt * 64;
        if (jt >= nj - 2) {
#pragma unroll
            for (int nt = 0; nt < 8; ++nt) {
                const int jc = j0 + nt * 8 + (lane & 3) * 2;
#pragma unroll
                for (int r = 0; r < 4; ++r) {
                    const int i = i0 + r0 + (r >> 1) * 8;
                    if (jc + (r & 1) > i) S[nt][r] = -1e30f;
                }
            }
        }

        // ---- online softmax (rows: r0, r0+8) ----
        float rm0 = -1e30f, rm1 = -1e30f;
#pragma unroll
        for (int nt = 0; nt < 8; ++nt) {
            rm0 = fmaxf(rm0, fmaxf(S[nt][0], S[nt][1]));
            rm1 = fmaxf(rm1, fmaxf(S[nt][2], S[nt][3]));
        }
        rm0 = fmaxf(rm0, __shfl_xor_sync(0xffffffffu, rm0, 1));
        rm0 = fmaxf(rm0, __shfl_xor_sync(0xffffffffu, rm0, 2));
        rm1 = fmaxf(rm1, __shfl_xor_sync(0xffffffffu, rm1, 1));
        rm1 = fmaxf(rm1, __shfl_xor_sync(0xffffffffu, rm1, 2));

        const float mn0 = fmaxf(m_[0], rm0);
        const float mn1 = fmaxf(m_[1], rm1);
        const float al0 = __expf(m_[0] - mn0);
        const float al1 = __expf(m_[1] - mn1);
        float rs0 = 0.0f, rs1 = 0.0f;
#pragma unroll
        for (int nt = 0; nt < 8; ++nt) {
            S[nt][0] = __expf(S[nt][0] - mn0);
            S[nt][1] = __expf(S[nt][1] - mn0);
            S[nt][2] = __expf(S[nt][2] - mn1);
            S[nt][3] = __expf(S[nt][3] - mn1);
            rs0 += S[nt][0] + S[nt][1];
            rs1 += S[nt][2] + S[nt][3];
        }
        rs0 += __shfl_xor_sync(0xffffffffu, rs0, 1);
        rs0 += __shfl_xor_sync(0xffffffffu, rs0, 2);
        rs1 += __shfl_xor_sync(0xffffffffu, rs1, 1);
        rs1 += __shfl_xor_sync(0xffffffffu, rs1, 2);

        l_[0] = l_[0] * al0 + rs0;
        l_[1] = l_[1] * al1 + rs1;
        m_[0] = mn0; m_[1] = mn1;

#pragma unroll
        for (int nt = 0; nt < 16; ++nt) {
            O[nt][0] *= al0; O[nt][1] *= al0;
            O[nt][2] *= al1; O[nt][3] *= al1;
        }

        // ---- O += P V  (single-pass fp16) ----
#pragma unroll
        for (int kc = 0; kc < 4; ++kc) {
            uint32_t pa[4];
            pa[0] = packhf(S[2 * kc][0],     S[2 * kc][1]);
            pa[1] = packhf(S[2 * kc][2],     S[2 * kc][3]);
            pa[2] = packhf(S[2 * kc + 1][0], S[2 * kc + 1][1]);
            pa[3] = packhf(S[2 * kc + 1][2], S[2 * kc + 1][3]);
#pragma unroll
            for (int dt2 = 0; dt2 < 8; ++dt2) {
                uint32_t vb[4];
                ldmx4(vb, stg + FK_BYTES +
                          (dt2 * 16 + lrB) * 144 + kc * 32 + cB16 * 16);
                mma16816h(O[2 * dt2],     pa, vb[0], vb[1]);
                mma16816h(O[2 * dt2 + 1], pa, vb[2], vb[3]);
            }
        }
    }

    // ---- epilogue: normalize, fp16 store to s_af [B,N,E] ----
#pragma unroll
    for (int rh = 0; rh < 2; ++rh) {
        const int i = i0 + r0 + rh * 8;
        const float inv = 1.0f / l_[rh];
#pragma unroll
        for (int nt = 0; nt < 16; ++nt) {
            const int d = nt * 8 + (lane & 3) * 2;
            const size_t idx = ((size_t)(b * NN + i)) * EE + h * DD + d;
            __half hp[2];
            hp[0] = __float2half(O[nt][2 * rh] * inv);
            hp[1] = __float2half(O[nt][2 * rh + 1] * inv);
            *(uint32_t*)(s_af + idx) = *(const uint32_t*)hp;
        }
    }
}

// ---------------------------------------------------------------------------
// Launch
// ---------------------------------------------------------------------------
extern "C" void kernel_launch(void* const* d_in, const int* in_sizes, int n_in,
                              void* d_out, int out_size)
{
    const float* x    = (const float*)d_in[0];
    const float* Wq   = (const float*)d_in[1];
    const float* Wkv  = (const float*)d_in[2];
    const float* Wout = (const float*)d_in[3];
    float* out = (float*)d_out;

    void *xf, *wqf, *wkf, *wof, *af;
    cudaGetSymbolAddress(&xf, s_xf);
    cudaGetSymbolAddress(&wqf, s_wqf);
    cudaGetSymbolAddress(&wkf, s_wkf);
    cudaGetSymbolAddress(&wof, s_wof);
    cudaGetSymbolAddress(&af, s_af);

    // One merged convert launch for all four inputs
    split_all_kernel<<<(N4_TOT + 255) / 256, 256>>>(x, Wq, Wkv, Wout);

    cudaFuncSetAttribute(gemm_mma<0>, cudaFuncAttributeMaxDynamicSharedMemorySize, GEMM_SMEM);
    cudaFuncSetAttribute(gemm_mma<3>, cudaFuncAttributeMaxDynamicSharedMemorySize, GEMM_SMEM);

    // Merged QKV projection: grid.x covers [Q | K | V] column tiles
    gemm_mma<3><<<dim3(3 * EE / 128, MTOT / 128), 256, GEMM_SMEM>>>(
        (const __half*)xf, (const __half*)wqf, (const __half*)wkf, nullptr);

    cudaFuncSetAttribute(flash_mma, cudaFuncAttributeMaxDynamicSharedMemorySize,
                         FLASH2_SMEM);
    flash_mma<<<dim3(NN / 128, BB * HH), 256, FLASH2_SMEM>>>();

    // Output projection
    gemm_mma<0><<<dim3(EE / 128, MTOT / 128), 256, GEMM_SMEM>>>(
        (const __half*)af, (const __half*)wof, nullptr, out);
}

// round 16
// speedup vs baseline: 1.1193x; 1.1193x over previous
#include <cuda_runtime.h>
#include <cuda_bf16.h>
#include <cuda_fp16.h>
#include <cstdint>

// Problem constants
#define BB 2
#define NN 2048
#define EE 2048
#define HH 16
#define DD 128
#define MTOT (BB * NN)
#define SCALE 0.08838834764831843f

// ---------------------------------------------------------------------------
// Device scratch (allocation-free rule)
// ---------------------------------------------------------------------------
__device__ __half g_qf[(size_t)BB * HH * NN * DD];   // Q fp16 [B,H,N,D] (pre-scaled)
__device__ __half g_kf[(size_t)BB * HH * NN * DD];   // K fp16 [B,H,N,D]
__device__ __half g_vtf[(size_t)BB * HH * DD * NN];  // V fp16 [B,H,D,N]

__device__ __half s_xf[8388608];    // x    fp16 [M,K]
__device__ __half s_wqf[4194304];   // Wq   fp16 [E,K]
__device__ __half s_wkf[8388608];   // Wkv  fp16 [2E,K]
__device__ __half s_wof[4194304];   // Wout fp16 [E,K]
__device__ __half s_af[8388608];    // attn fp16 [B,N,E]

// ---------------------------------------------------------------------------
// Helpers
// ---------------------------------------------------------------------------
__device__ __forceinline__ uint32_t smem_u32(const void* p) {
    uint32_t a;
    asm("{ .reg .u64 t; cvta.to.shared.u64 t, %1; cvt.u32.u64 %0, t; }"
        : "=r"(a) : "l"(p));
    return a;
}
__device__ __forceinline__ void cp16(uint32_t dst, const void* src) {
    asm volatile("cp.async.cg.shared.global [%0], [%1], 16;"
                 :: "r"(dst), "l"(src));
}
__device__ __forceinline__ void cp_commit() {
    asm volatile("cp.async.commit_group;");
}
__device__ __forceinline__ uint32_t sw128(uint32_t off) {  // SW128 for 128B rows
    return off ^ ((off >> 3) & 0x70);
}
__device__ __forceinline__ void ldmx4(uint32_t* f, uint32_t addr) {
    asm volatile("ldmatrix.sync.aligned.m8n8.x4.shared.b16 {%0,%1,%2,%3}, [%4];"
                 : "=r"(f[0]), "=r"(f[1]), "=r"(f[2]), "=r"(f[3]) : "r"(addr));
}
// fp16 MMA
__device__ __forceinline__ void mma16816h(float* c, const uint32_t* a,
                                          uint32_t b0, uint32_t b1) {
    asm volatile(
        "mma.sync.aligned.m16n8k16.row.col.f32.f16.f16.f32 "
        "{%0,%1,%2,%3}, {%4,%5,%6,%7}, {%8,%9}, {%0,%1,%2,%3};"
        : "+f"(c[0]), "+f"(c[1]), "+f"(c[2]), "+f"(c[3])
        : "r"(a[0]), "r"(a[1]), "r"(a[2]), "r"(a[3]), "r"(b0), "r"(b1));
}
__device__ __forceinline__ uint32_t packhf(float a, float b) {
    __half2 t = __floats2half2_rn(a, b);
    return *(uint32_t*)&t;
}

// ---------------------------------------------------------------------------
// Merged convert kernel: all four fp32 inputs -> fp16 in one launch
// ---------------------------------------------------------------------------
#define N4_X  2097152
#define N4_WQ 1048576
#define N4_WK 2097152
#define N4_WO 1048576
#define N4_TOT (N4_X + N4_WQ + N4_WK + N4_WO)   // 6291456

__global__ __launch_bounds__(256) void split_all_kernel(
    const float* __restrict__ x, const float* __restrict__ wq,
    const float* __restrict__ wk, const float* __restrict__ wo)
{
    int i = blockIdx.x * blockDim.x + threadIdx.x;
    if (i >= N4_TOT) return;
    const float* src;
    __half* dst;
    int off;
    if (i < N4_X) {
        src = x; dst = s_xf; off = i;
    } else if (i < N4_X + N4_WQ) {
        src = wq; dst = s_wqf; off = i - N4_X;
    } else if (i < N4_X + N4_WQ + N4_WK) {
        src = wk; dst = s_wkf; off = i - N4_X - N4_WQ;
    } else {
        src = wo; dst = s_wof; off = i - N4_X - N4_WQ - N4_WK;
    }
    float4 v = ((const float4*)src)[off];
    __half h[4];
    h[0] = __float2half(v.x); h[1] = __float2half(v.y);
    h[2] = __float2half(v.z); h[3] = __float2half(v.w);
    ((uint2*)dst)[off] = *(const uint2*)h;
}

// ---------------------------------------------------------------------------
// fp16 single-pass GEMM via mma.sync.
// K-chunk 64 (128B rows, SW128), 2-stage ring, ONE barrier/iter, 2 CTAs/SM.
// MODE 0: Cout fp32 [M,E]  (Wout projection: A=s_af, W=s_wof)
// MODE 3: merged QKV: blockIdx.x selects Q / K / V target + weight matrix
// ---------------------------------------------------------------------------
#define GTILE 16384                // 128 rows x 128B (64 fp16)
#define GSTAGE (2 * GTILE)         // 32768
#define GEMM_SMEM 67584            // max(2 stages = 64KB, epilogue 128*132*4)

__device__ __forceinline__ void load_chunk(
    uint32_t stage, const __half* Af, const __half* Wf,
    int m0, int wrow0, int k0, int tid)
{
#pragma unroll
    for (int t = 0; t < 4; ++t) {
        const int c = tid + t * 256;           // 0..1023 : 16B chunks per tile
        const int row = c >> 3;
        const int ch = c & 7;
        const uint32_t so = sw128((uint32_t)(row * 128 + ch * 16));
        cp16(stage + so, Af + (size_t)(m0 + row) * EE + k0 + ch * 8);
        cp16(stage + GTILE + so, Wf + (size_t)(wrow0 + row) * EE + k0 + ch * 8);
    }
}

template <int MODE>
__global__ void __launch_bounds__(256, 2) gemm_mma(
    const __half* __restrict__ Af,
    const __half* __restrict__ Wqf, const __half* __restrict__ Wkf,
    float* __restrict__ Cout)
{
    extern __shared__ char smem[];
    const uint32_t sb = smem_u32(smem);
    const int tid = threadIdx.x;
    const int lane = tid & 31;
    const int w = tid >> 5;
    const int wm = w >> 2;
    const int wn = w & 3;
    const int m0 = blockIdx.y * 128;
    const int n0 = blockIdx.x * 128;

    const __half* Wf;
    int wrow0, ek;
    if (MODE == 0) {
        Wf = Wqf; wrow0 = n0; ek = 3;
    } else {
        if (n0 < EE) { Wf = Wqf; wrow0 = n0; ek = 0; }
        else {
            Wf = Wkf; wrow0 = n0 - EE;
            ek = (wrow0 < EE) ? 1 : 2;
        }
    }

    float acc[4][4][4];
#pragma unroll
    for (int i = 0; i < 4; ++i)
#pragma unroll
        for (int j = 0; j < 4; ++j)
#pragma unroll
            for (int r = 0; r < 4; ++r) acc[i][j][r] = 0.0f;

    const int sel = lane >> 3;
    const int lrow8 = ((sel & 1) << 3) + (lane & 7);
    const int lkc = sel >> 1;

    const int nk = EE >> 6;     // 32 iterations of K=64
    load_chunk(sb, Af, Wf, m0, wrow0, 0, tid);
    cp_commit();

    for (int kt = 0; kt < nk; ++kt) {
        const uint32_t stage = sb + (kt & 1) * GSTAGE;

        asm volatile("cp.async.wait_group 0;");
        __syncthreads();

        // Prefetch kt+1 into the stage read at kt-1 (reads done pre-barrier)
        if (kt + 1 < nk) {
            load_chunk(sb + ((kt + 1) & 1) * GSTAGE, Af, Wf, m0, wrow0,
                       (kt + 1) << 6, tid);
            cp_commit();
        }

#pragma unroll
        for (int ks = 0; ks < 4; ++ks) {
            const int kchunk = ks * 2 + lkc;
            uint32_t af[4][4];
#pragma unroll
            for (int i = 0; i < 4; ++i) {
                const int r = wm * 64 + i * 16 + lrow8;
                const uint32_t off = sw128((uint32_t)(r * 128 + kchunk * 16));
                ldmx4(af[i], stage + off);
            }
            uint32_t bf[2][4];
#pragma unroll
            for (int j2 = 0; j2 < 2; ++j2) {
                const int r = wn * 32 + j2 * 16 + lrow8;
                const uint32_t off = sw128((uint32_t)(r * 128 + kchunk * 16));
                ldmx4(bf[j2], stage + GTILE + off);
            }
#pragma unroll
            for (int i = 0; i < 4; ++i) {
#pragma unroll
                for (int j = 0; j < 4; ++j) {
                    const int j2 = j >> 1, jo = j & 1;
                    mma16816h(acc[i][j], af[i], bf[j2][jo], bf[j2][2 + jo]);
                }
            }
        }
    }
    __syncthreads();   // protect epilogue smem reuse vs last stage reads

    // ---- Epilogue ----
    float* Ss = (float*)smem;   // [128][132]
#pragma unroll
    for (int i = 0; i < 4; ++i) {
        const int r = wm * 64 + i * 16 + (lane >> 2);
#pragma unroll
        for (int j = 0; j < 4; ++j) {
            const int cc = wn * 32 + j * 8 + 2 * (lane & 3);
            Ss[r * 132 + cc]           = acc[i][j][0];
            Ss[r * 132 + cc + 1]       = acc[i][j][1];
            Ss[(r + 8) * 132 + cc]     = acc[i][j][2];
            Ss[(r + 8) * 132 + cc + 1] = acc[i][j][3];
        }
    }
    __syncthreads();

    const int b = m0 >> 11;
    const int nbase = m0 & (NN - 1);

    if (ek == 3) {
#pragma unroll
        for (int it = 0; it < 16; ++it) {
            const int f = it * 256 + tid;
            const int r = f >> 5;
            const int c4 = (f & 31) << 2;
            float4 v = *(const float4*)(Ss + r * 132 + c4);
            *(float4*)(Cout + (size_t)(m0 + r) * EE + n0 + c4) = v;
        }
    } else if (ek == 0 || ek == 1) {
        const int h = wrow0 >> 7;
        __half* dq = (ek == 0 ? g_qf : g_kf) +
            ((size_t)(b * HH + h) * NN + nbase) * DD;
        const float sc = (ek == 0) ? SCALE : 1.0f;   // pre-scale Q by D^-0.5
#pragma unroll
        for (int it = 0; it < 16; ++it) {
            const int f = it * 256 + tid;
            const int r = f >> 5;
            const int c4 = (f & 31) << 2;
            float4 v = *(const float4*)(Ss + r * 132 + c4);
            __half hq[4];
            hq[0] = __float2half(v.x * sc); hq[1] = __float2half(v.y * sc);
            hq[2] = __float2half(v.z * sc); hq[3] = __float2half(v.w * sc);
            *(uint2*)(dq + (size_t)r * DD + c4) = *(const uint2*)hq;
        }
    } else {
        // V -> g_vtf fp16, transposed [B,H,D,N]
        const int h2 = (wrow0 - EE) >> 7;
        const int col = tid >> 1;
        const int rh2 = tid & 1;
        __half* dst = g_vtf + ((size_t)(b * HH + h2) * DD + col) * NN +
                      nbase + (rh2 << 6);
#pragma unroll
        for (int i = 0; i < 16; ++i) {
            const int r = (rh2 << 6) + (i << 2);
            __half v4[4];
            v4[0] = __float2half(Ss[(r + 0) * 132 + col]);
            v4[1] = __float2half(Ss[(r + 1) * 132 + col]);
            v4[2] = __float2half(Ss[(r + 2) * 132 + col]);
            v4[3] = __float2half(Ss[(r + 3) * 132 + col]);
            *(uint2*)(dst + (i << 2)) = *(const uint2*)v4;
        }
    }
}

// ---------------------------------------------------------------------------
// Flash attention v3: single-pass fp16 mma.sync for QK^T and PV.
// Br=128 (8 warps x 16 rows), Bc=64, D=128. 2 CTAs/SM.
// ONE barrier per KV tile (prefetch issued after barrier).
// Q pre-scaled by D^-0.5 at projection — no scale loop here.
// Smem: Q [128x272B] | 2 stages of {K 64x272B; Vt 128x144B}
// ---------------------------------------------------------------------------
#define FQ_BYTES 34816              // 128*272
#define FK_BYTES 17408              // 64*272
#define FV_BYTES 18432              // 128*144
#define FSTAGE (FK_BYTES + FV_BYTES)                // 35840
#define FLASH2_SMEM (FQ_BYTES + 2 * FSTAGE)         // 106496

__device__ __forceinline__ void load_kv(
    uint32_t stg, const __half* Kf, const __half* Vf, int j0, int tid)
{
#pragma unroll
    for (int t = 0; t < 4; ++t) {
        const int c = t * 256 + tid;        // 0..1023
        const int row = c >> 4, ch = c & 15;
        cp16(stg + row * 272 + ch * 16,
             Kf + (size_t)(j0 + row) * DD + ch * 8);
    }
#pragma unroll
    for (int t = 0; t < 4; ++t) {
        const int c = t * 256 + tid;        // 0..1023
        const int drow = c >> 3, ch = c & 7;
        cp16(stg + FK_BYTES + drow * 144 + ch * 16,
             Vf + (size_t)drow * NN + j0 + ch * 8);
    }
}

__global__ void __launch_bounds__(256, 2) flash_mma()
{
    extern __shared__ char smc[];
    const uint32_t sb = smem_u32(smc);
    const int tid = threadIdx.x;
    const int lane = tid & 31;
    const int w = tid >> 5;
    const int bh = blockIdx.y;
    const int b = bh >> 4, h = bh & (HH - 1);
    const int qt = (gridDim.x - 1) - blockIdx.x;   // long tiles first
    const int i0 = qt * 128;

    const __half* Qf = g_qf + (size_t)bh * NN * DD;
    const __half* Kf = g_kf + (size_t)bh * NN * DD;
    const __half* Vf = g_vtf + (size_t)bh * DD * NN;

    // Q tile
#pragma unroll
    for (int t = 0; t < 8; ++t) {
        const int c = t * 256 + tid;        // 0..2047
        const int row = c >> 4, ch = c & 15;
        cp16(sb + row * 272 + ch * 16,
             Qf + (size_t)(i0 + row) * DD + ch * 8);
    }
    load_kv(sb + FQ_BYTES, Kf, Vf, 0, tid);
    cp_commit();

    const int nj = 2 * qt + 2;
    float m_[2] = {-1e30f, -1e30f}, l_[2] = {0.0f, 0.0f};
    float O[16][4];
#pragma unroll
    for (int nt = 0; nt < 16; ++nt)
#pragma unroll
        for (int r = 0; r < 4; ++r) O[nt][r] = 0.0f;

    const int r0 = w * 16 + (lane >> 2);

    for (int jt = 0; jt < nj; ++jt) {
        const uint32_t stg = sb + FQ_BYTES + (jt & 1) * FSTAGE;

        asm volatile("cp.async.wait_group 0;");
        __syncthreads();

        // Prefetch next KV into the stage read at jt-1 (reads done pre-barrier)
        if (jt + 1 < nj) {
            load_kv(sb + FQ_BYTES + ((jt + 1) & 1) * FSTAGE,
                    Kf, Vf, (jt + 1) * 64, tid);
            cp_commit();
        }

        // ---- S = Q K^T (single-pass fp16; Q pre-scaled) ----
        float S[8][4];
#pragma unroll
        for (int nt = 0; nt < 8; ++nt)
#pragma unroll
            for (int r = 0; r < 4; ++r) S[nt][r] = 0.0f;

        const int lrA = w * 16 + ((lane >> 3) & 1) * 8 + (lane & 7);
        const int cA16 = (lane >> 4) & 1;
        const int lrB = ((lane >> 4) & 1) * 8 + (lane & 7);
        const int cB16 = (lane >> 3) & 1;

#pragma unroll
        for (int ks = 0; ks < 8; ++ks) {
            uint32_t aq[4];
            ldmx4(aq, sb + lrA * 272 + ks * 32 + cA16 * 16);
#pragma unroll
            for (int jn2 = 0; jn2 < 4; ++jn2) {
                uint32_t bk[4];
                ldmx4(bk, stg + (jn2 * 16 + lrB) * 272 + ks * 32 + cB16 * 16);
                mma16816h(S[2 * jn2],     aq, bk[0], bk[1]);
                mma16816h(S[2 * jn2 + 1], aq, bk[2], bk[3]);
            }
        }

        // ---- causal mask (last two KV tiles only) ----
        const int j0 = jt * 64;
        if (jt >= nj - 2) {
#pragma unroll
            for (int nt = 0; nt < 8; ++nt) {
                const int jc = j0 + nt * 8 + (lane & 3) * 2;
#pragma unroll
                for (int r = 0; r < 4; ++r) {
                    const int i = i0 + r0 + (r >> 1) * 8;
                    if (jc + (r & 1) > i) S[nt][r] = -1e30f;
                }
            }
        }

        // ---- online softmax (rows: r0, r0+8) ----
        float rm0 = -1e30f, rm1 = -1e30f;
#pragma unroll
        for (int nt = 0; nt < 8; ++nt) {
            rm0 = fmaxf(rm0, fmaxf(S[nt][0], S[nt][1]));
            rm1 = fmaxf(rm1, fmaxf(S[nt][2], S[nt][3]));
        }
        rm0 = fmaxf(rm0, __shfl_xor_sync(0xffffffffu, rm0, 1));
        rm0 = fmaxf(rm0, __shfl_xor_sync(0xffffffffu, rm0, 2));
        rm1 = fmaxf(rm1, __shfl_xor_sync(0xffffffffu, rm1, 1));
        rm1 = fmaxf(rm1, __shfl_xor_sync(0xffffffffu, rm1, 2));

        const float mn0 = fmaxf(m_[0], rm0);
        const float mn1 = fmaxf(m_[1], rm1);
        const float al0 = __expf(m_[0] - mn0);
        const float al1 = __expf(m_[1] - mn1);
        float rs0 = 0.0f, rs1 = 0.0f;
#pragma unroll
        for (int nt = 0; nt < 8; ++nt) {
            S[nt][0] = __expf(S[nt][0] - mn0);
            S[nt][1] = __expf(S[nt][1] - mn0);
            S[nt][2] = __expf(S[nt][2] - mn1);
            S[nt][3] = __expf(S[nt][3] - mn1);
            rs0 += S[nt][0] + S[nt][1];
            rs1 += S[nt][2] + S[nt][3];
        }
        rs0 += __shfl_xor_sync(0xffffffffu, rs0, 1);
        rs0 += __shfl_xor_sync(0xffffffffu, rs0, 2);
        rs1 += __shfl_xor_sync(0xffffffffu, rs1, 1);
        rs1 += __shfl_xor_sync(0xffffffffu, rs1, 2);

        l_[0] = l_[0] * al0 + rs0;
        l_[1] = l_[1] * al1 + rs1;
        m_[0] = mn0; m_[1] = mn1;

#pragma unroll
        for (int nt = 0; nt < 16; ++nt) {
            O[nt][0] *= al0; O[nt][1] *= al0;
            O[nt][2] *= al1; O[nt][3] *= al1;
        }

        // ---- O += P V  (single-pass fp16) ----
#pragma unroll
        for (int kc = 0; kc < 4; ++kc) {
            uint32_t pa[4];
            pa[0] = packhf(S[2 * kc][0],     S[2 * kc][1]);
            pa[1] = packhf(S[2 * kc][2],     S[2 * kc][3]);
            pa[2] = packhf(S[2 * kc + 1][0], S[2 * kc + 1][1]);
            pa[3] = packhf(S[2 * kc + 1][2], S[2 * kc + 1][3]);
#pragma unroll
            for (int dt2 = 0; dt2 < 8; ++dt2) {
                uint32_t vb[4];
                ldmx4(vb, stg + FK_BYTES +
                          (dt2 * 16 + lrB) * 144 + kc * 32 + cB16 * 16);
                mma16816h(O[2 * dt2],     pa, vb[0], vb[1]);
                mma16816h(O[2 * dt2 + 1], pa, vb[2], vb[3]);
            }
        }
    }

    // ---- epilogue: normalize, fp16 store to s_af [B,N,E] ----
#pragma unroll
    for (int rh = 0; rh < 2; ++rh) {
        const int i = i0 + r0 + rh * 8;
        const float inv = 1.0f / l_[rh];
#pragma unroll
        for (int nt = 0; nt < 16; ++nt) {
            const int d = nt * 8 + (lane & 3) * 2;
            const size_t idx = ((size_t)(b * NN + i)) * EE + h * DD + d;
            __half hp[2];
            hp[0] = __float2half(O[nt][2 * rh] * inv);
            hp[1] = __float2half(O[nt][2 * rh + 1] * inv);
            *(uint32_t*)(s_af + idx) = *(const uint32_t*)hp;
        }
    }
}

// ---------------------------------------------------------------------------
// Launch
// ---------------------------------------------------------------------------
extern "C" void kernel_launch(void* const* d_in, const int* in_sizes, int n_in,
                              void* d_out, int out_size)
{
    const float* x    = (const float*)d_in[0];
    const float* Wq   = (const float*)d_in[1];
    const float* Wkv  = (const float*)d_in[2];
    const float* Wout = (const float*)d_in[3];
    float* out = (float*)d_out;

    void *xf, *wqf, *wkf, *wof, *af;
    cudaGetSymbolAddress(&xf, s_xf);
    cudaGetSymbolAddress(&wqf, s_wqf);
    cudaGetSymbolAddress(&wkf, s_wkf);
    cudaGetSymbolAddress(&wof, s_wof);
    cudaGetSymbolAddress(&af, s_af);

    // One merged convert launch for all four inputs
    split_all_kernel<<<(N4_TOT + 255) / 256, 256>>>(x, Wq, Wkv, Wout);

    cudaFuncSetAttribute(gemm_mma<0>, cudaFuncAttributeMaxDynamicSharedMemorySize, GEMM_SMEM);
    cudaFuncSetAttribute(gemm_mma<3>, cudaFuncAttributeMaxDynamicSharedMemorySize, GEMM_SMEM);

    // Merged QKV projection: grid.x covers [Q | K | V] column tiles
    gemm_mma<3><<<dim3(3 * EE / 128, MTOT / 128), 256, GEMM_SMEM>>>(
        (const __half*)xf, (const __half*)wqf, (const __half*)wkf, nullptr);

    cudaFuncSetAttribute(flash_mma, cudaFuncAttributeMaxDynamicSharedMemorySize,
                         FLASH2_SMEM);
    flash_mma<<<dim3(NN / 128, BB * HH), 256, FLASH2_SMEM>>>();

    // Output projection
    gemm_mma<0><<<dim3(EE / 128, MTOT / 128), 256, GEMM_SMEM>>>(
        (const __half*)af, (const __half*)wof, nullptr, out);
}